// round 1
// baseline (speedup 1.0000x reference)
#include <cuda_runtime.h>
#include <math.h>

#define BB    32
#define HRESD 56
#define WRESD 56
#define CCH   256
#define LLEN  (HRESD*WRESD)          // 3136
#define ROWS  (BB*LLEN)              // 100352
#define NHH   8
#define HD    32
#define GW    7
#define NWT   49                     // tokens per window
#define NWIN  64                     // windows per image (8x8)
#define BWIN  (BB*NWIN)              // 2048
#define HID   1024
#define QSCALE 0.17677669529663687f  // 32^-0.5

// ---------------- scratch (device globals: no cudaMalloc allowed) ----------
__device__ float g_xn  [(size_t)ROWS*CCH];       // LN output (reused for LN1 and LN2)
__device__ float g_q   [(size_t)BWIN*NHH*NWT*HD];
__device__ float g_k   [(size_t)BWIN*NHH*NWT*HD];
__device__ float g_v   [(size_t)BWIN*NHH*NWT*HD];
__device__ float g_awin[(size_t)ROWS*CCH];       // attention out, windowed row order
__device__ float g_x1  [(size_t)ROWS*CCH];       // shortcut + attn branch
__device__ float g_hid [(size_t)ROWS*HID];       // fc1 activations
__device__ float g_pos [169*NHH];                // dynamic position bias table

// ---------------- DynamicPosBias MLP (tiny) --------------------------------
__device__ __forceinline__ void pos_stage(float* t, const float* g, const float* b,
                                          const float* w, const float* wb, int outn) {
    float mu = 0.f;
    #pragma unroll
    for (int p = 0; p < 16; p++) mu += t[p];
    mu *= (1.f/16.f);
    float var = 0.f;
    #pragma unroll
    for (int p = 0; p < 16; p++) { float d = t[p]-mu; var += d*d; }
    var *= (1.f/16.f);
    float inv = rsqrtf(var + 1e-5f);
    float u[16];
    #pragma unroll
    for (int p = 0; p < 16; p++) {
        float z = (t[p]-mu)*inv*g[p] + b[p];
        u[p] = fmaxf(z, 0.f);
    }
    for (int q = 0; q < outn; q++) {
        float s = wb[q];
        #pragma unroll
        for (int p = 0; p < 16; p++) s += u[p]*w[p*outn + q];
        t[q] = s;
    }
}

__global__ void pos_mlp_kernel(const float* pw, const float* pb,
                               const float* g1, const float* b1, const float* w1, const float* wb1,
                               const float* g2, const float* b2, const float* w2, const float* wb2,
                               const float* g3, const float* b3, const float* w3, const float* wb3) {
    int i = threadIdx.x;
    if (i >= 169) return;
    float bh = (float)(i/13 - 6);
    float bw = (float)(i%13 - 6);
    float t[16];
    #pragma unroll
    for (int p = 0; p < 16; p++) t[p] = bh*pw[p] + bw*pw[16+p] + pb[p];
    pos_stage(t, g1, b1, w1, wb1, 16);
    pos_stage(t, g2, b2, w2, wb2, 16);
    pos_stage(t, g3, b3, w3, wb3, NHH);
    #pragma unroll
    for (int h = 0; h < NHH; h++) g_pos[i*NHH + h] = t[h];
}

// ---------------- LayerNorm (row per block, C=256, 256 threads) ------------
__global__ void ln_kernel(const float* __restrict__ xin,
                          const float* __restrict__ gamma,
                          const float* __restrict__ beta, int src) {
    int r = blockIdx.x, t = threadIdx.x;
    const float* in = src ? g_x1 : xin;
    float v = in[(size_t)r*CCH + t];
    __shared__ float red[8];
    __shared__ float stat[2];

    float s = v;
    #pragma unroll
    for (int o = 16; o; o >>= 1) s += __shfl_xor_sync(0xffffffffu, s, o);
    if ((t & 31) == 0) red[t >> 5] = s;
    __syncthreads();
    if (t == 0) {
        float tot = 0.f;
        #pragma unroll
        for (int i = 0; i < 8; i++) tot += red[i];
        stat[0] = tot * (1.f/256.f);
    }
    __syncthreads();
    float mu = stat[0];
    float d = v - mu;
    s = d*d;
    #pragma unroll
    for (int o = 16; o; o >>= 1) s += __shfl_xor_sync(0xffffffffu, s, o);
    if ((t & 31) == 0) red[t >> 5] = s;
    __syncthreads();
    if (t == 0) {
        float tot = 0.f;
        #pragma unroll
        for (int i = 0; i < 8; i++) tot += red[i];
        stat[1] = tot * (1.f/256.f);
    }
    __syncthreads();
    float inv = rsqrtf(stat[1] + 1e-5f);
    g_xn[(size_t)r*CCH + t] = d*inv*gamma[t] + beta[t];
}

// ---------------- Tiled fp32 GEMM, 64x64x16, 4x4 per thread ----------------
// EPI: 0 = QKV (A=g_xn, fused window permute + q scale)
//      1 = PROJ (A=g_awin, fused un-window + residual with X=x -> g_x1)
//      2 = FC1  (A=g_xn, fused exact GELU -> g_hid)
//      3 = FC2  (A=g_hid, fused residual with g_x1 -> Out)
template<int EPI, int NC, int KC>
__global__ void gemm64(const float* __restrict__ Bm,
                       const float* __restrict__ bias,
                       const float* __restrict__ X,
                       float* __restrict__ Out) {
    __shared__ float As[16][64];
    __shared__ float Bs[16][64];
    const float* A = (EPI == 1) ? g_awin : (EPI == 3 ? g_hid : g_xn);

    int tid = threadIdx.x;
    int tx = tid & 15, ty = tid >> 4;
    int rowBase = blockIdx.y * 64;
    int colBase = blockIdx.x * 64;

    int aRow  = rowBase + (tid >> 2);
    int aColQ = (tid & 3) * 4;
    int bRow  = tid >> 4;
    int bColQ = (tid & 15) * 4;

    float acc[4][4];
    #pragma unroll
    for (int i = 0; i < 4; i++)
        #pragma unroll
        for (int j = 0; j < 4; j++) acc[i][j] = 0.f;

    for (int kt = 0; kt < KC; kt += 16) {
        float4 av = *(const float4*)&A[(size_t)aRow*KC + kt + aColQ];
        As[aColQ+0][tid>>2] = av.x;
        As[aColQ+1][tid>>2] = av.y;
        As[aColQ+2][tid>>2] = av.z;
        As[aColQ+3][tid>>2] = av.w;
        float4 bv = *(const float4*)&Bm[(size_t)(kt + bRow)*NC + colBase + bColQ];
        *(float4*)&Bs[bRow][bColQ] = bv;
        __syncthreads();
        #pragma unroll
        for (int k = 0; k < 16; k++) {
            float4 a4 = *(const float4*)&As[k][ty*4];
            float4 b4 = *(const float4*)&Bs[k][tx*4];
            float ar[4] = {a4.x, a4.y, a4.z, a4.w};
            float br[4] = {b4.x, b4.y, b4.z, b4.w};
            #pragma unroll
            for (int i = 0; i < 4; i++)
                #pragma unroll
                for (int j = 0; j < 4; j++) acc[i][j] += ar[i]*br[j];
        }
        __syncthreads();
    }

    #pragma unroll
    for (int i = 0; i < 4; i++) {
        int r = rowBase + ty*4 + i;
        #pragma unroll
        for (int j = 0; j < 4; j++) {
            int c = colBase + tx*4 + j;
            float val = acc[i][j] + bias[c];
            if (EPI == 0) {
                // row r is a plain token row; scatter to windowed q/k/v
                int b  = r / LLEN, l = r % LLEN;
                int hh = l / WRESD, wc = l % WRESD;
                int wh = hh / GW, ii = hh % GW;
                int wn = wc / GW, jj = wc % GW;
                int Bidx = b*NWIN + wh*8 + wn;
                int n = ii*GW + jj;
                int sect = c >> 8;
                int head = (c >> 5) & 7;
                int d    = c & 31;
                size_t idx = (((size_t)Bidx*NHH + head)*NWT + n)*HD + d;
                if (sect == 0)      g_q[idx] = val * QSCALE;
                else if (sect == 1) g_k[idx] = val;
                else                g_v[idx] = val;
            } else if (EPI == 1) {
                // row r is windowed: map back to (b, l), add shortcut x
                int Bidx = r / NWT, n = r % NWT;
                int b  = Bidx / NWIN, wi = Bidx % NWIN;
                int wh = wi / 8, wn = wi % 8;
                int ii = n / GW, jj = n % GW;
                int l  = (wh*GW + ii)*WRESD + wn*GW + jj;
                size_t idx = ((size_t)b*LLEN + l)*CCH + c;
                g_x1[idx] = X[idx] + val;
            } else if (EPI == 2) {
                float ge = 0.5f*val*(1.f + erff(val*0.70710678118654752f));
                g_hid[(size_t)r*HID + c] = ge;
            } else {
                size_t idx = (size_t)r*CCH + c;
                Out[idx] = g_x1[idx] + val;
            }
        }
    }
}

// ---------------- Windowed attention: one block per (window, head) ---------
__global__ void attn_kernel() {
    __shared__ float qs[NWT][HD];
    __shared__ float ks[NWT][HD];
    __shared__ float vs[NWT][HD];
    __shared__ float at[NWT][NWT+1];

    int blk  = blockIdx.x;              // Bidx*8 + head
    int head = blk & 7;
    int Bidx = blk >> 3;
    size_t base = (size_t)blk * NWT * HD;
    int tid = threadIdx.x;

    for (int i = tid; i < NWT*HD; i += 256) {
        int r = i / HD, d = i % HD;
        qs[r][d] = g_q[base + i];
        ks[r][d] = g_k[base + i];
        vs[r][d] = g_v[base + i];
    }
    __syncthreads();

    for (int idx = tid; idx < NWT*NWT; idx += 256) {
        int r = idx / NWT, m = idx % NWT;
        float s = 0.f;
        #pragma unroll
        for (int d = 0; d < HD; d++) s += qs[r][d]*ks[m][d];
        int dh = r/GW - m/GW + 6;
        int dw = r%GW - m%GW + 6;
        s += g_pos[(dh*13 + dw)*NHH + head];
        at[r][m] = s;
    }
    __syncthreads();

    if (tid < NWT) {
        float mx = -1e30f;
        for (int m = 0; m < NWT; m++) mx = fmaxf(mx, at[tid][m]);
        float sum = 0.f;
        for (int m = 0; m < NWT; m++) {
            float e = expf(at[tid][m] - mx);
            at[tid][m] = e;
            sum += e;
        }
        float inv = 1.f/sum;
        for (int m = 0; m < NWT; m++) at[tid][m] *= inv;
    }
    __syncthreads();

    for (int idx = tid; idx < NWT*HD; idx += 256) {
        int r = idx / HD, d = idx % HD;
        float s = 0.f;
        #pragma unroll
        for (int m = 0; m < NWT; m++) s += at[r][m]*vs[m][d];
        size_t o = ((size_t)Bidx*NWT + r)*CCH + head*HD + d;
        g_awin[o] = s;
    }
}

// ---------------- launch ----------------------------------------------------
extern "C" void kernel_launch(void* const* d_in, const int* in_sizes, int n_in,
                              void* d_out, int out_size) {
    const float* x        = (const float*)d_in[0];
    const float* norm1_g  = (const float*)d_in[1];
    const float* norm1_b  = (const float*)d_in[2];
    const float* qkv_w    = (const float*)d_in[3];
    const float* qkv_b    = (const float*)d_in[4];
    const float* proj_w   = (const float*)d_in[5];
    const float* proj_b   = (const float*)d_in[6];
    const float* pos_pw   = (const float*)d_in[7];
    const float* pos_pb   = (const float*)d_in[8];
    const float* p1g      = (const float*)d_in[9];
    const float* p1b      = (const float*)d_in[10];
    const float* p1w      = (const float*)d_in[11];
    const float* p1wb     = (const float*)d_in[12];
    const float* p2g      = (const float*)d_in[13];
    const float* p2b      = (const float*)d_in[14];
    const float* p2w      = (const float*)d_in[15];
    const float* p2wb     = (const float*)d_in[16];
    const float* p3g      = (const float*)d_in[17];
    const float* p3b      = (const float*)d_in[18];
    const float* p3w      = (const float*)d_in[19];
    const float* p3wb     = (const float*)d_in[20];
    const float* norm2_g  = (const float*)d_in[21];
    const float* norm2_b  = (const float*)d_in[22];
    const float* fc1_w    = (const float*)d_in[23];
    const float* fc1_b    = (const float*)d_in[24];
    const float* fc2_w    = (const float*)d_in[25];
    const float* fc2_b    = (const float*)d_in[26];
    float* out = (float*)d_out;

    // 1. dynamic position bias table (169 x 8)
    pos_mlp_kernel<<<1, 192>>>(pos_pw, pos_pb, p1g, p1b, p1w, p1wb,
                               p2g, p2b, p2w, p2wb, p3g, p3b, p3w, p3wb);
    // 2. LN1
    ln_kernel<<<ROWS, 256>>>(x, norm1_g, norm1_b, 0);
    // 3. QKV GEMM (fused window permute + q scale)
    gemm64<0, 768, 256><<<dim3(12, ROWS/64), 256>>>(qkv_w, qkv_b, nullptr, nullptr);
    // 4. windowed attention
    attn_kernel<<<BWIN*NHH, 256>>>();
    // 5. proj GEMM (fused un-window + residual)
    gemm64<1, 256, 256><<<dim3(4, ROWS/64), 256>>>(proj_w, proj_b, x, nullptr);
    // 6. LN2
    ln_kernel<<<ROWS, 256>>>(nullptr, norm2_g, norm2_b, 1);
    // 7. FC1 + GELU
    gemm64<2, 1024, 256><<<dim3(16, ROWS/64), 256>>>(fc1_w, fc1_b, nullptr, nullptr);
    // 8. FC2 + final residual
    gemm64<3, 256, 1024><<<dim3(4, ROWS/64), 256>>>(fc2_w, fc2_b, nullptr, out);
}

// round 3
// speedup vs baseline: 1.7081x; 1.7081x over previous
#include <cuda_runtime.h>
#include <cuda_bf16.h>
#include <math.h>
#include <stdint.h>

#define BB    32
#define HRESD 56
#define WRESD 56
#define CCH   256
#define LLEN  (HRESD*WRESD)          // 3136
#define ROWS  (BB*LLEN)              // 100352
#define NHH   8
#define HD    32
#define GW    7
#define NWT   49
#define NWIN  64
#define BWIN  (BB*NWIN)              // 2048
#define HID   1024
#define QSCALE 0.17677669529663687f

// ---------------- scratch ---------------------------------------------------
__device__ float g_xn  [(size_t)ROWS*CCH];
__device__ float g_q   [(size_t)BWIN*NHH*NWT*HD];
__device__ float g_k   [(size_t)BWIN*NHH*NWT*HD];
__device__ float g_v   [(size_t)BWIN*NHH*NWT*HD];
__device__ float g_awin[(size_t)ROWS*CCH];
__device__ float g_x1  [(size_t)ROWS*CCH];
__device__ float g_hid [(size_t)ROWS*HID];
__device__ float g_pos [169*NHH];

// ---------------- helpers ----------------------------------------------------
__device__ __forceinline__ uint32_t smem_u32(const void* p) {
    uint32_t a;
    asm("{ .reg .u64 t; cvta.to.shared.u64 t, %1; cvt.u32.u64 %0, t; }" : "=r"(a) : "l"(p));
    return a;
}
__device__ __forceinline__ uint32_t pk(float a, float b) {
    __nv_bfloat162 t = __floats2bfloat162_rn(a, b);
    return *(uint32_t*)&t;
}
__device__ __forceinline__ float bres(float v) {
    return v - __bfloat162float(__float2bfloat16_rn(v));
}
__device__ __forceinline__ void ldsm4(uint32_t* r, uint32_t addr) {
    asm volatile("ldmatrix.sync.aligned.m8n8.x4.shared.b16 {%0,%1,%2,%3}, [%4];"
                 : "=r"(r[0]), "=r"(r[1]), "=r"(r[2]), "=r"(r[3]) : "r"(addr));
}
__device__ __forceinline__ void mma16816(float* c, const uint32_t* a, const uint32_t* b) {
    asm volatile("mma.sync.aligned.m16n8k16.row.col.f32.bf16.bf16.f32 "
                 "{%0,%1,%2,%3}, {%4,%5,%6,%7}, {%8,%9}, {%0,%1,%2,%3};"
                 : "+f"(c[0]), "+f"(c[1]), "+f"(c[2]), "+f"(c[3])
                 : "r"(a[0]), "r"(a[1]), "r"(a[2]), "r"(a[3]), "r"(b[0]), "r"(b[1]));
}

#define SSTR 40   // smem row stride in bf16 elements (32 + 8 pad)

// ---------------- mma.sync GEMM: 128x128 tile, BK=32, bf16 hi/lo split ------
// EPI: 0=QKV  1=PROJ  2=FC1+GELU  3=FC2+res
template<int EPI, int NC, int KC>
__global__ __launch_bounds__(256, 1) void gemm_mma(const float* __restrict__ Bm,
                                                   const float* __restrict__ bias,
                                                   const float* __restrict__ X,
                                                   float* __restrict__ Out) {
    __shared__ __align__(16) __nv_bfloat16 Ah[128*SSTR];
    __shared__ __align__(16) __nv_bfloat16 Al[128*SSTR];
    __shared__ __align__(16) __nv_bfloat16 Bh[128*SSTR];
    __shared__ __align__(16) __nv_bfloat16 Bl[128*SSTR];

    const float* A = (EPI == 1) ? g_awin : (EPI == 3 ? g_hid : g_xn);

    int tid  = threadIdx.x;
    int lane = tid & 31, wid = tid >> 5;
    int warpM = wid & 3, warpN = wid >> 2;        // 4 x 2 warp grid
    int rbase = blockIdx.y * 128;
    int cbase = blockIdx.x * 128;

    uint32_t ahb = smem_u32(Ah), alb = smem_u32(Al);
    uint32_t bhb = smem_u32(Bh), blb = smem_u32(Bl);

    float acc[2][8][4];
    #pragma unroll
    for (int mi = 0; mi < 2; mi++)
        #pragma unroll
        for (int nj = 0; nj < 8; nj++)
            #pragma unroll
            for (int e = 0; e < 4; e++) acc[mi][nj][e] = 0.f;

    // staging registers
    float4 sa[4];
    float  sb[16];
    const int bn = tid & 127, bks = (tid >> 7) * 16;

    auto loadTile = [&](int kt) {
        #pragma unroll
        for (int u = 0; u < 4; u++) {
            int c = tid + u*256;
            int row = c >> 3, colq = (c & 7) * 4;
            sa[u] = *(const float4*)&A[(size_t)(rbase + row)*KC + kt + colq];
        }
        const float* bp = &Bm[cbase + bn];
        #pragma unroll
        for (int k = 0; k < 16; k++)
            sb[k] = bp[(size_t)(kt + bks + k)*NC];
    };
    auto storeTile = [&]() {
        #pragma unroll
        for (int u = 0; u < 4; u++) {
            int c = tid + u*256;
            int row = c >> 3, colq = (c & 7) * 4;
            int off = row*SSTR + colq;
            *(uint2*)&Ah[off] = make_uint2(pk(sa[u].x, sa[u].y), pk(sa[u].z, sa[u].w));
            *(uint2*)&Al[off] = make_uint2(pk(bres(sa[u].x), bres(sa[u].y)),
                                           pk(bres(sa[u].z), bres(sa[u].w)));
        }
        int boff = bn*SSTR + bks;
        #pragma unroll
        for (int k = 0; k < 16; k += 2) {
            *(uint32_t*)&Bh[boff + k] = pk(sb[k], sb[k+1]);
            *(uint32_t*)&Bl[boff + k] = pk(bres(sb[k]), bres(sb[k+1]));
        }
    };

    const int T = KC / 32;
    loadTile(0);

    for (int t = 0; t < T; t++) {
        __syncthreads();
        storeTile();
        __syncthreads();
        if (t + 1 < T) loadTile((t + 1) * 32);

        #pragma unroll
        for (int k0 = 0; k0 < 32; k0 += 16) {
            uint32_t a_h[2][4], a_l[2][4], b_h[8][2], b_l[8][2];
            #pragma unroll
            for (int mi = 0; mi < 2; mi++) {
                int row = warpM*32 + mi*16 + (lane & 15);
                int col = k0 + ((lane & 16) >> 1);
                uint32_t o = (uint32_t)(row*SSTR + col) * 2;
                ldsm4(a_h[mi], ahb + o);
                ldsm4(a_l[mi], alb + o);
            }
            #pragma unroll
            for (int j = 0; j < 4; j++) {
                int row = warpN*64 + j*16 + (lane & 7) + ((lane & 16) >> 1);
                int col = k0 + (lane & 8);
                uint32_t o = (uint32_t)(row*SSTR + col) * 2;
                uint32_t r[4];
                ldsm4(r, bhb + o);
                b_h[j*2][0] = r[0]; b_h[j*2][1] = r[1];
                b_h[j*2+1][0] = r[2]; b_h[j*2+1][1] = r[3];
                ldsm4(r, blb + o);
                b_l[j*2][0] = r[0]; b_l[j*2][1] = r[1];
                b_l[j*2+1][0] = r[2]; b_l[j*2+1][1] = r[3];
            }
            #pragma unroll
            for (int mi = 0; mi < 2; mi++)
                #pragma unroll
                for (int nj = 0; nj < 8; nj++) {
                    mma16816(acc[mi][nj], a_h[mi], b_h[nj]);
                    mma16816(acc[mi][nj], a_h[mi], b_l[nj]);
                    mma16816(acc[mi][nj], a_l[mi], b_h[nj]);
                }
        }
    }

    // ---- epilogue -----------------------------------------------------------
    #pragma unroll
    for (int mi = 0; mi < 2; mi++)
        #pragma unroll
        for (int nj = 0; nj < 8; nj++)
            #pragma unroll
            for (int e = 0; e < 4; e++) {
                int row = rbase + warpM*32 + mi*16 + (lane >> 2) + ((e >= 2) ? 8 : 0);
                int c   = cbase + warpN*64 + nj*8 + (lane & 3)*2 + (e & 1);
                float val = acc[mi][nj][e] + bias[c];
                if (EPI == 0) {
                    int b  = row / LLEN, l = row % LLEN;
                    int hh = l / WRESD, wc = l % WRESD;
                    int wh = hh / GW, ii = hh % GW;
                    int wn = wc / GW, jj = wc % GW;
                    int Bidx = b*NWIN + wh*8 + wn;
                    int n = ii*GW + jj;
                    int sect = c >> 8;
                    int head = (c >> 5) & 7;
                    int d    = c & 31;
                    size_t idx = (((size_t)Bidx*NHH + head)*NWT + n)*HD + d;
                    if (sect == 0)      g_q[idx] = val * QSCALE;
                    else if (sect == 1) g_k[idx] = val;
                    else                g_v[idx] = val;
                } else if (EPI == 1) {
                    int Bidx = row / NWT, n = row % NWT;
                    int b  = Bidx / NWIN, wi = Bidx % NWIN;
                    int wh = wi / 8, wn = wi % 8;
                    int ii = n / GW, jj = n % GW;
                    int l  = (wh*GW + ii)*WRESD + wn*GW + jj;
                    size_t idx = ((size_t)b*LLEN + l)*CCH + c;
                    g_x1[idx] = X[idx] + val;
                } else if (EPI == 2) {
                    float ge = 0.5f*val*(1.f + erff(val*0.70710678118654752f));
                    g_hid[(size_t)row*HID + c] = ge;
                } else {
                    size_t idx = (size_t)row*CCH + c;
                    Out[idx] = g_x1[idx] + val;
                }
            }
}

// ---------------- DynamicPosBias MLP ----------------------------------------
__device__ __forceinline__ void pos_stage(float* t, const float* g, const float* b,
                                          const float* w, const float* wb, int outn) {
    float mu = 0.f;
    #pragma unroll
    for (int p = 0; p < 16; p++) mu += t[p];
    mu *= (1.f/16.f);
    float var = 0.f;
    #pragma unroll
    for (int p = 0; p < 16; p++) { float d = t[p]-mu; var += d*d; }
    var *= (1.f/16.f);
    float inv = rsqrtf(var + 1e-5f);
    float u[16];
    #pragma unroll
    for (int p = 0; p < 16; p++) {
        float z = (t[p]-mu)*inv*g[p] + b[p];
        u[p] = fmaxf(z, 0.f);
    }
    for (int q = 0; q < outn; q++) {
        float s = wb[q];
        #pragma unroll
        for (int p = 0; p < 16; p++) s += u[p]*w[p*outn + q];
        t[q] = s;
    }
}

__global__ void pos_mlp_kernel(const float* pw, const float* pb,
                               const float* g1, const float* b1, const float* w1, const float* wb1,
                               const float* g2, const float* b2, const float* w2, const float* wb2,
                               const float* g3, const float* b3, const float* w3, const float* wb3) {
    int i = threadIdx.x;
    if (i >= 169) return;
    float bh = (float)(i/13 - 6);
    float bw = (float)(i%13 - 6);
    float t[16];
    #pragma unroll
    for (int p = 0; p < 16; p++) t[p] = bh*pw[p] + bw*pw[16+p] + pb[p];
    pos_stage(t, g1, b1, w1, wb1, 16);
    pos_stage(t, g2, b2, w2, wb2, 16);
    pos_stage(t, g3, b3, w3, wb3, NHH);
    #pragma unroll
    for (int h = 0; h < NHH; h++) g_pos[i*NHH + h] = t[h];
}

// ---------------- LayerNorm -------------------------------------------------
__global__ void ln_kernel(const float* __restrict__ xin,
                          const float* __restrict__ gamma,
                          const float* __restrict__ beta, int src) {
    int r = blockIdx.x, t = threadIdx.x;
    const float* in = src ? g_x1 : xin;
    float v = in[(size_t)r*CCH + t];
    __shared__ float red[8];
    __shared__ float stat[2];
    float s = v;
    #pragma unroll
    for (int o = 16; o; o >>= 1) s += __shfl_xor_sync(0xffffffffu, s, o);
    if ((t & 31) == 0) red[t >> 5] = s;
    __syncthreads();
    if (t == 0) {
        float tot = 0.f;
        #pragma unroll
        for (int i = 0; i < 8; i++) tot += red[i];
        stat[0] = tot * (1.f/256.f);
    }
    __syncthreads();
    float mu = stat[0];
    float d = v - mu;
    s = d*d;
    #pragma unroll
    for (int o = 16; o; o >>= 1) s += __shfl_xor_sync(0xffffffffu, s, o);
    if ((t & 31) == 0) red[t >> 5] = s;
    __syncthreads();
    if (t == 0) {
        float tot = 0.f;
        #pragma unroll
        for (int i = 0; i < 8; i++) tot += red[i];
        stat[1] = tot * (1.f/256.f);
    }
    __syncthreads();
    float inv = rsqrtf(stat[1] + 1e-5f);
    g_xn[(size_t)r*CCH + t] = d*inv*gamma[t] + beta[t];
}

// ---------------- Windowed attention ----------------------------------------
__global__ void attn_kernel() {
    __shared__ float qs[NWT][HD];
    __shared__ float ks[NWT][HD];
    __shared__ float vs[NWT][HD];
    __shared__ float at[NWT][NWT+1];

    int blk  = blockIdx.x;
    int head = blk & 7;
    int Bidx = blk >> 3;
    size_t base = (size_t)blk * NWT * HD;
    int tid = threadIdx.x;

    for (int i = tid; i < NWT*HD; i += 256) {
        int r = i / HD, d = i % HD;
        qs[r][d] = g_q[base + i];
        ks[r][d] = g_k[base + i];
        vs[r][d] = g_v[base + i];
    }
    __syncthreads();

    for (int idx = tid; idx < NWT*NWT; idx += 256) {
        int r = idx / NWT, m = idx % NWT;
        float s = 0.f;
        #pragma unroll
        for (int d = 0; d < HD; d++) s += qs[r][d]*ks[m][d];
        int dh = r/GW - m/GW + 6;
        int dw = r%GW - m%GW + 6;
        s += g_pos[(dh*13 + dw)*NHH + head];
        at[r][m] = s;
    }
    __syncthreads();

    if (tid < NWT) {
        float mx = -1e30f;
        for (int m = 0; m < NWT; m++) mx = fmaxf(mx, at[tid][m]);
        float sum = 0.f;
        for (int m = 0; m < NWT; m++) {
            float e = expf(at[tid][m] - mx);
            at[tid][m] = e;
            sum += e;
        }
        float inv = 1.f/sum;
        for (int m = 0; m < NWT; m++) at[tid][m] *= inv;
    }
    __syncthreads();

    for (int idx = tid; idx < NWT*HD; idx += 256) {
        int r = idx / HD, d = idx % HD;
        float s = 0.f;
        #pragma unroll
        for (int m = 0; m < NWT; m++) s += at[r][m]*vs[m][d];
        size_t o = ((size_t)Bidx*NWT + r)*CCH + head*HD + d;
        g_awin[o] = s;
    }
}

// ---------------- launch ----------------------------------------------------
extern "C" void kernel_launch(void* const* d_in, const int* in_sizes, int n_in,
                              void* d_out, int out_size) {
    const float* x        = (const float*)d_in[0];
    const float* norm1_g  = (const float*)d_in[1];
    const float* norm1_b  = (const float*)d_in[2];
    const float* qkv_w    = (const float*)d_in[3];
    const float* qkv_b    = (const float*)d_in[4];
    const float* proj_w   = (const float*)d_in[5];
    const float* proj_b   = (const float*)d_in[6];
    const float* pos_pw   = (const float*)d_in[7];
    const float* pos_pb   = (const float*)d_in[8];
    const float* p1g      = (const float*)d_in[9];
    const float* p1b      = (const float*)d_in[10];
    const float* p1w      = (const float*)d_in[11];
    const float* p1wb     = (const float*)d_in[12];
    const float* p2g      = (const float*)d_in[13];
    const float* p2b      = (const float*)d_in[14];
    const float* p2w      = (const float*)d_in[15];
    const float* p2wb     = (const float*)d_in[16];
    const float* p3g      = (const float*)d_in[17];
    const float* p3b      = (const float*)d_in[18];
    const float* p3w      = (const float*)d_in[19];
    const float* p3wb     = (const float*)d_in[20];
    const float* norm2_g  = (const float*)d_in[21];
    const float* norm2_b  = (const float*)d_in[22];
    const float* fc1_w    = (const float*)d_in[23];
    const float* fc1_b    = (const float*)d_in[24];
    const float* fc2_w    = (const float*)d_in[25];
    const float* fc2_b    = (const float*)d_in[26];
    float* out = (float*)d_out;

    pos_mlp_kernel<<<1, 192>>>(pos_pw, pos_pb, p1g, p1b, p1w, p1wb,
                               p2g, p2b, p2w, p2wb, p3g, p3b, p3w, p3wb);
    ln_kernel<<<ROWS, 256>>>(x, norm1_g, norm1_b, 0);
    gemm_mma<0,768,256><<<dim3(6, ROWS/128), 256>>>(qkv_w, qkv_b, nullptr, nullptr);
    attn_kernel<<<BWIN*NHH, 256>>>();
    gemm_mma<1,256,256><<<dim3(2, ROWS/128), 256>>>(proj_w, proj_b, x, nullptr);
    ln_kernel<<<ROWS, 256>>>(nullptr, norm2_g, norm2_b, 1);
    gemm_mma<2,1024,256><<<dim3(8, ROWS/128), 256>>>(fc1_w, fc1_b, nullptr, nullptr);
    gemm_mma<3,256,1024><<<dim3(2, ROWS/128), 256>>>(fc2_w, fc2_b, nullptr, out);
}